// round 16
// baseline (speedup 1.0000x reference)
#include <cuda_runtime.h>
#include <math.h>
#include <float.h>
#include <stdint.h>

#define NB    32
#define MROWS 100000
#define WC    64
#define RR    9
#define NIF   138
#define DIN   512
#define NBLK  18             // blocks per batch; 18*32 = 576 = single wave at 4/SM
#define PUBROWS 5440         // publisher chunk (85 tiles) -- smaller to offset iface work
#define CHUNK2  5568         // other blocks (87 tiles); 5440 + 17*5568 >= 100000
#define NCAND (NBLK*8)       // 144
#define NPROD 16
#define NPOOL (NPROD*8 + RR) // 137
#define NSTAGE 3
#define TROWS  64
#define TBYTES (TROWS * WC * 4)     // 16384
#define SMEM_DYN (NSTAGE * TBYTES)  // 48KB

// -------- scratch (no allocation allowed) --------
__device__ float g_q[NB][WC];
__device__ float g_rows[NB][RR][WC];
__device__ float g_cand_d[NB][NCAND];
__device__ int   g_cand_i[NB][NCAND];
__device__ int   g_qready[NB];       // zero-init; reset by ticket block
__device__ int   g_tick_sc[NB];

__device__ __forceinline__ bool lt_pair(float d1, int i1, float d2, int i2) {
    return d1 < d2 || (d1 == d2 && i1 < i2);
}

__device__ __forceinline__ uint32_t smem_u32(const void* p) {
    uint32_t a;
    asm("{ .reg .u64 t; cvta.to.shared.u64 t, %1; cvt.u32.u64 %0, t; }" : "=r"(a) : "l"(p));
    return a;
}
__device__ __forceinline__ void mbar_init(uint32_t addr, uint32_t cnt) {
    asm volatile("mbarrier.init.shared.b64 [%0], %1;" :: "r"(addr), "r"(cnt) : "memory");
}
__device__ __forceinline__ void mbar_expect_tx(uint32_t addr, uint32_t bytes) {
    asm volatile("mbarrier.arrive.expect_tx.shared.b64 _, [%0], %1;" :: "r"(addr), "r"(bytes) : "memory");
}
__device__ __forceinline__ void mbar_wait(uint32_t addr, uint32_t parity) {
    asm volatile(
        "{\n\t.reg .pred P;\n\t"
        "WAIT_%=:\n\t"
        "mbarrier.try_wait.parity.acquire.cta.shared::cta.b64 P, [%0], %1, 0x989680;\n\t"
        "@P bra.uni DONE_%=;\n\t"
        "bra.uni WAIT_%=;\n\t"
        "DONE_%=:\n\t}"
        :: "r"(addr), "r"(parity) : "memory");
}
__device__ __forceinline__ void bulk_g2s(uint32_t dst, const void* src, uint32_t bytes, uint32_t mbar) {
    asm volatile("cp.async.bulk.shared::cta.global.mbarrier::complete_tx::bytes [%0], [%1], %2, [%3];"
                 :: "r"(dst), "l"(src), "r"(bytes), "r"(mbar) : "memory");
}

// ================= Single fused kernel =================
// All blocks: issue TMA prologue immediately. Block x==0 per batch computes
// the iface GEMM + updated rows (hidden under everyone's prefetch), publishes
// q via flag; others spin. Scan core identical to the R13 winner.
__global__ void __launch_bounds__(256, 4) k_scan(
    const float* __restrict__ mem, const int* __restrict__ rpos,
    float* __restrict__ out,
    const float* __restrict__ xi, const float* __restrict__ Wm,
    const float* __restrict__ b_lin, const float* __restrict__ usage,
    const float* __restrict__ read_w, const float* __restrict__ rvec)
{
    extern __shared__ __align__(128) char dynsmem[];
    const int b = blockIdx.y;
    const int bx = blockIdx.x;
    const int row0 = (bx == 0) ? 0 : PUBROWS + (bx - 1) * CHUNK2;
    const int row_end = min(row0 + ((bx == 0) ? PUBROWS : CHUNK2), MROWS);
    const int tid = threadIdx.x;
    const int lane = tid & 31;
    const int warp = tid >> 5;

    __shared__ __align__(8) unsigned long long mbar[NSTAGE];
    __shared__ int srp[RR];
    __shared__ float sd[NCAND];
    __shared__ int   si[NCAND];
    __shared__ int slast;
    __shared__ int sel[8];
    __shared__ float sx[DIN];
    __shared__ float sif[NIF];
    __shared__ float sww[RR];
    __shared__ float swv[WC];

    if (tid < RR) srp[tid] = rpos[b * RR + tid];
    if (tid < NSTAGE) mbar_init(smem_u32(&mbar[tid]), 1);
    __syncthreads();

    const int nrows = row_end - row0;
    const int ntiles = (nrows + TROWS - 1) / TROWS;
    const float* base = mem + (size_t)b * MROWS * WC;
    const uint32_t smem_base = smem_u32(dynsmem);

    // prologue: issue first NSTAGE tiles immediately (does not need q)
    if (tid == 0) {
        int npro = min(NSTAGE, ntiles);
        for (int t = 0; t < npro; ++t) {
            int tr = min(TROWS, nrows - t * TROWS);
            uint32_t bytes = (uint32_t)tr * WC * 4;
            uint32_t mb = smem_u32(&mbar[t]);
            mbar_expect_tx(mb, bytes);
            bulk_g2s(smem_base + t * TBYTES, base + (size_t)(row0 + t * TROWS) * WC, bytes, mb);
        }
    }

    // ---- iface publish / spin (overlapped with the TMA prefetch above) ----
    if (bx == 0) {
        for (int i = tid; i < DIN; i += 256) sx[i] = xi[b * DIN + i];
        __syncthreads();
        if (tid < NIF) {
            float acc = b_lin[tid];
            #pragma unroll 8
            for (int d = 0; d < DIN; d++) acc = fmaf(sx[d], Wm[d * NIF + tid], acc);
            sif[tid] = acc;
            if (tid < WC) g_q[b][tid] = acc;
            if (tid >= WC && tid < 2 * WC) swv[tid - WC] = acc;
        }
        __syncthreads();
        if (tid == 0) {
            float wg = 1.f / (1.f + expf(-sif[NIF - 1]));
            float rel[RR]; float minu = INFINITY;
            #pragma unroll
            for (int k = 0; k < RR; k++) {
                rel[k] = usage[(size_t)b * MROWS + srp[k]];
                minu = fminf(minu, rel[k]);
            }
            #pragma unroll
            for (int k = 0; k < RR; k++) {
                float ig = 1.f / (1.f + expf(-sif[2 * WC + k]));
                float I  = (rel[k] == minu) ? 1.f : 0.f;
                sww[k] = wg * (ig * read_w[b * RR + k] + (1.f - ig) * I);
            }
        }
        __syncthreads();
        for (int t = tid; t < RR * WC; t += 256) {
            int k = t >> 6, w = t & 63;
            g_rows[b][k][w] = rvec[(b * RR + k) * WC + w] + sww[k] * swv[w];
        }
        __threadfence();     // all threads: make g_q/g_rows globally visible
        __syncthreads();
        if (tid == 0) atomicExch(&g_qready[b], 1);
    } else {
        if (tid == 0) { while (atomicAdd(&g_qready[b], 0) == 0) __nanosleep(64); }
        __syncthreads();
        __threadfence();     // order subsequent loads after observed flag
    }

    // q piece: floats [(tid&15)*4, +4)
    float4 qp = __ldcg((const float4*)&g_q[b][(tid & 15) * 4]);

    float ld[8]; int lix[8];
    #pragma unroll
    for (int k = 0; k < 8; k++) { ld[k] = INFINITY; lix[k] = 0x7fffffff; }
    const bool is_prod = ((lane & 15) == 0);
    const int rbase = tid >> 4;

    for (int t = 0; t < ntiles; ++t) {
        int s = t % NSTAGE;
        uint32_t mb = smem_u32(&mbar[s]);
        mbar_wait(mb, (t / NSTAGE) & 1);

        // eager issue of tile (t-1)+NSTAGE into drained slot (t-1)%NSTAGE
        if (t > 0 && tid == 0) {
            int tn = (t - 1) + NSTAGE;
            if (tn < ntiles) {
                int s2 = (t - 1) % NSTAGE;
                int tr = min(TROWS, nrows - tn * TROWS);
                uint32_t bytes = (uint32_t)tr * WC * 4;
                uint32_t mb2 = smem_u32(&mbar[s2]);
                mbar_expect_tx(mb2, bytes);
                bulk_g2s(smem_base + s2 * TBYTES, base + (size_t)(row0 + tn * TROWS) * WC, bytes, mb2);
            }
        }

        const char* stg = dynsmem + s * TBYTES;
        float acc0, acc1, acc2, acc3;
        {
            const float4 v0 = *(const float4*)(stg + tid * 16);
            const float4 v1 = *(const float4*)(stg + tid * 16 + 4096);
            const float4 v2 = *(const float4*)(stg + tid * 16 + 8192);
            const float4 v3 = *(const float4*)(stg + tid * 16 + 12288);
            float dx;
            dx = v0.x - qp.x; acc0  = dx * dx;
            dx = v0.y - qp.y; acc0 += dx * dx;
            dx = v0.z - qp.z; acc0 += dx * dx;
            dx = v0.w - qp.w; acc0 += dx * dx;
            dx = v1.x - qp.x; acc1  = dx * dx;
            dx = v1.y - qp.y; acc1 += dx * dx;
            dx = v1.z - qp.z; acc1 += dx * dx;
            dx = v1.w - qp.w; acc1 += dx * dx;
            dx = v2.x - qp.x; acc2  = dx * dx;
            dx = v2.y - qp.y; acc2 += dx * dx;
            dx = v2.z - qp.z; acc2 += dx * dx;
            dx = v2.w - qp.w; acc2 += dx * dx;
            dx = v3.x - qp.x; acc3  = dx * dx;
            dx = v3.y - qp.y; acc3 += dx * dx;
            dx = v3.z - qp.z; acc3 += dx * dx;
            dx = v3.w - qp.w; acc3 += dx * dx;
        }
        #pragma unroll
        for (int off = 1; off <= 8; off <<= 1) {
            acc0 += __shfl_xor_sync(0xffffffffu, acc0, off);
            acc1 += __shfl_xor_sync(0xffffffffu, acc1, off);
            acc2 += __shfl_xor_sync(0xffffffffu, acc2, off);
            acc3 += __shfl_xor_sync(0xffffffffu, acc3, off);
        }
        if (is_prod) {
            int g0 = row0 + t * TROWS + rbase;
            float av[4] = {acc0, acc1, acc2, acc3};
            #pragma unroll
            for (int k = 0; k < 4; k++) {
                int gr = g0 + 16 * k;
                float cv = av[k];
                if (gr < row_end && lt_pair(cv, gr, ld[7], lix[7])) {
                    bool stale = false;
                    #pragma unroll
                    for (int j = 0; j < RR; j++) stale |= (srp[j] == gr);
                    if (!stale) {
                        int ci = gr;
                        #pragma unroll
                        for (int j = 0; j < 8; j++) {
                            bool sw = lt_pair(cv, ci, ld[j], lix[j]);
                            float td = ld[j]; int ti = lix[j];
                            if (sw) { ld[j] = cv; lix[j] = ci; cv = td; ci = ti; }
                        }
                    }
                }
            }
        }
        __syncthreads();   // stage s fully consumed
    }

    // producers dump sorted-8 to pool [0,128)
    if (is_prod) {
        #pragma unroll
        for (int k = 0; k < 8; k++) { sd[rbase * 8 + k] = ld[k]; si[rbase * 8 + k] = lix[k]; }
    }

    // warp 0: patch candidates for rp rows in range (slots [128,137))
    if (warp == 0) {
        #pragma unroll
        for (int k = 0; k < RR; k++) {
            int rr = srp[k];
            bool use = (rr >= row0 && rr < row_end);
            #pragma unroll
            for (int k2 = k + 1; k2 < RR; k2++) use &= (srp[k2] != rr);  // last write wins
            float accv = 0.f;
            if (lane < 16) {
                float4 g0 = __ldcg((const float4*)&g_rows[b][k][lane * 4]);
                float dx;
                dx = g0.x - qp.x; accv  = dx * dx;
                dx = g0.y - qp.y; accv += dx * dx;
                dx = g0.z - qp.z; accv += dx * dx;
                dx = g0.w - qp.w; accv += dx * dx;
                #pragma unroll
                for (int off = 1; off <= 8; off <<= 1)
                    accv += __shfl_xor_sync(0xFFFFu, accv, off);
            }
            if (lane == 0) {
                sd[NPROD * 8 + k] = use ? accv : INFINITY;
                si[NPROD * 8 + k] = use ? rr   : 0x7fffffff;
            }
        }
    }
    __syncthreads();

    // merge pool (137) -> block top-8 -> global candidates
    if (tid < 32) {
        int l = tid;
        for (int s = 0; s < 8; s++) {
            float bd = INFINITY; int bi = 0x7fffffff; int bs = -1;
            for (int k = l; k < NPOOL; k += 32)
                if (lt_pair(sd[k], si[k], bd, bi)) { bd = sd[k]; bi = si[k]; bs = k; }
            #pragma unroll
            for (int off = 16; off; off >>= 1) {
                float od = __shfl_xor_sync(0xffffffffu, bd, off);
                int   oi = __shfl_xor_sync(0xffffffffu, bi, off);
                int   os = __shfl_xor_sync(0xffffffffu, bs, off);
                if (lt_pair(od, oi, bd, bi)) { bd = od; bi = oi; bs = os; }
            }
            if (l == 0) {
                g_cand_d[b][bx * 8 + s] = bd;
                g_cand_i[b][bx * 8 + s] = bi;
                if (bs >= 0) sd[bs] = INFINITY;
            }
            __syncwarp();
        }
    }

    // ticket: last block of batch b does final merge + gather, resets flags
    __threadfence();
    if (tid == 0) slast = (atomicAdd(&g_tick_sc[b], 1) == NBLK - 1);
    __syncthreads();
    if (!slast) return;
    if (tid == 0) { g_tick_sc[b] = 0; g_qready[b] = 0; }

    if (tid < NCAND) {
        sd[tid] = __ldcg(&g_cand_d[b][tid]);
        si[tid] = __ldcg(&g_cand_i[b][tid]);
    }
    __syncthreads();

    if (tid < 32) {
        int l = tid;
        for (int s = 0; s < 8; s++) {
            float bd = INFINITY; int bi = 0x7fffffff; int bs = -1;
            for (int k = l; k < NCAND; k += 32)
                if (lt_pair(sd[k], si[k], bd, bi)) { bd = sd[k]; bi = si[k]; bs = k; }
            #pragma unroll
            for (int off = 16; off; off >>= 1) {
                float od = __shfl_xor_sync(0xffffffffu, bd, off);
                int   oi = __shfl_xor_sync(0xffffffffu, bi, off);
                int   os = __shfl_xor_sync(0xffffffffu, bs, off);
                if (lt_pair(od, oi, bd, bi)) { bd = od; bi = oi; bs = os; }
            }
            if (l == 0) { sel[s] = bi; if (bs >= 0) sd[bs] = INFINITY; }
            __syncwarp();
        }
    }
    __syncthreads();

    for (int t = tid; t < 8 * WC; t += blockDim.x) {
        int k = t >> 6, w = t & 63;
        int idx = sel[k];
        int src = -1;
        #pragma unroll
        for (int j = RR - 1; j >= 0; --j)
            if (src < 0 && srp[j] == idx) src = j;
        float v = (src >= 0) ? __ldcg(&g_rows[b][src][w])
                             : __ldcg(&mem[((size_t)b * MROWS + idx) * WC + w]);
        out[(b * 8 + k) * WC + w] = v;
    }
}

// ================= launcher =================
extern "C" void kernel_launch(void* const* d_in, const int* in_sizes, int n_in,
                              void* d_out, int out_size) {
    const float* xi     = (const float*)d_in[0];
    const float* Wm     = (const float*)d_in[1];
    const float* b_lin  = (const float*)d_in[2];
    const float* mem    = (const float*)d_in[3];
    const float* usage  = (const float*)d_in[4];
    const float* read_w = (const float*)d_in[5];
    const float* rvec   = (const float*)d_in[7];
    const int*   rpos   = (const int*)d_in[9];
    float* out = (float*)d_out;

    static int smem_set = 0;
    if (!smem_set) {
        cudaFuncSetAttribute(k_scan, cudaFuncAttributeMaxDynamicSharedMemorySize, SMEM_DYN);
        smem_set = 1;
    }

    k_scan<<<dim3(NBLK, NB), 256, SMEM_DYN>>>(mem, rpos, out, xi, Wm, b_lin,
                                              usage, read_w, rvec);
}

// round 17
// speedup vs baseline: 1.1747x; 1.1747x over previous
#include <cuda_runtime.h>
#include <math.h>
#include <float.h>
#include <stdint.h>

#define NB    32
#define MROWS 100000
#define WC    64
#define RR    9
#define NIF   138
#define DIN   512
#define NBLK  18             // 18*32 = 576 blocks = single wave at 4/SM (592 slots)
#define CHUNK 5556           // uniform; 18*5556 >= 100000
#define NCAND (NBLK*8)       // 144
#define NPROD 16
#define NPOOL (NPROD*8 + RR) // 137
#define NPART 4              // publisher blocks per batch (bx < 4)
#define NSTAGE 3
#define TROWS  64
#define TBYTES (TROWS * WC * 4)     // 16384
#define SMEM_DYN (NSTAGE * TBYTES)  // 48KB

// -------- scratch (no allocation allowed) --------
__device__ float g_part[NB][NPART][NIF];
__device__ float g_q[NB][WC];
__device__ float g_rows[NB][RR][WC];
__device__ float g_cand_d[NB][NCAND];
__device__ int   g_cand_i[NB][NCAND];
__device__ int   g_qready[NB];       // zero-init; reset by final ticket block
__device__ int   g_tick_if[NB];
__device__ int   g_tick_sc[NB];

__device__ __forceinline__ bool lt_pair(float d1, int i1, float d2, int i2) {
    return d1 < d2 || (d1 == d2 && i1 < i2);
}

__device__ __forceinline__ uint32_t smem_u32(const void* p) {
    uint32_t a;
    asm("{ .reg .u64 t; cvta.to.shared.u64 t, %1; cvt.u32.u64 %0, t; }" : "=r"(a) : "l"(p));
    return a;
}
__device__ __forceinline__ void mbar_init(uint32_t addr, uint32_t cnt) {
    asm volatile("mbarrier.init.shared.b64 [%0], %1;" :: "r"(addr), "r"(cnt) : "memory");
}
__device__ __forceinline__ void mbar_expect_tx(uint32_t addr, uint32_t bytes) {
    asm volatile("mbarrier.arrive.expect_tx.shared.b64 _, [%0], %1;" :: "r"(addr), "r"(bytes) : "memory");
}
__device__ __forceinline__ void mbar_wait(uint32_t addr, uint32_t parity) {
    asm volatile(
        "{\n\t.reg .pred P;\n\t"
        "WAIT_%=:\n\t"
        "mbarrier.try_wait.parity.acquire.cta.shared::cta.b64 P, [%0], %1, 0x989680;\n\t"
        "@P bra.uni DONE_%=;\n\t"
        "bra.uni WAIT_%=;\n\t"
        "DONE_%=:\n\t}"
        :: "r"(addr), "r"(parity) : "memory");
}
__device__ __forceinline__ void bulk_g2s(uint32_t dst, const void* src, uint32_t bytes, uint32_t mbar) {
    asm volatile("cp.async.bulk.shared::cta.global.mbarrier::complete_tx::bytes [%0], [%1], %2, [%3];"
                 :: "r"(dst), "l"(src), "r"(bytes), "r"(mbar) : "memory");
}

// ================= Single fused kernel =================
// All blocks issue their TMA prologue first (needs no q). Blocks bx<4 of each
// batch compute a 128-d-slice iface partial (~2.5us each); the last of the 4
// (atomic ticket) finishes + publishes q/g_rows, raising the flag. Others spin
// (their prefetch keeps DRAM busy). Scan core = R13 winner.
__global__ void __launch_bounds__(256, 4) k_scan(
    const float* __restrict__ mem, const int* __restrict__ rpos,
    float* __restrict__ out,
    const float* __restrict__ xi, const float* __restrict__ Wm,
    const float* __restrict__ b_lin, const float* __restrict__ usage,
    const float* __restrict__ read_w, const float* __restrict__ rvec)
{
    extern __shared__ __align__(128) char dynsmem[];
    const int b = blockIdx.y;
    const int bx = blockIdx.x;
    const int row0 = bx * CHUNK;
    const int row_end = min(row0 + CHUNK, MROWS);
    const int tid = threadIdx.x;
    const int lane = tid & 31;
    const int warp = tid >> 5;

    __shared__ __align__(8) unsigned long long mbar[NSTAGE];
    __shared__ int srp[RR];
    __shared__ float sd[NCAND];
    __shared__ int   si[NCAND];
    __shared__ int sflag;
    __shared__ int sel[8];
    __shared__ float sx[128];
    __shared__ float sif[NIF];
    __shared__ float sww[RR];
    __shared__ float swv[WC];

    if (tid < RR) srp[tid] = rpos[b * RR + tid];
    if (tid < NSTAGE) mbar_init(smem_u32(&mbar[tid]), 1);
    __syncthreads();

    const int nrows = row_end - row0;
    const int ntiles = (nrows + TROWS - 1) / TROWS;
    const float* base = mem + (size_t)b * MROWS * WC;
    const uint32_t smem_base = smem_u32(dynsmem);

    // ---- TMA prologue first: needs no q, keeps DRAM busy during iface ----
    if (tid == 0) {
        int npro = min(NSTAGE, ntiles);
        for (int t = 0; t < npro; ++t) {
            int tr = min(TROWS, nrows - t * TROWS);
            uint32_t bytes = (uint32_t)tr * WC * 4;
            uint32_t mb = smem_u32(&mbar[t]);
            mbar_expect_tx(mb, bytes);
            bulk_g2s(smem_base + t * TBYTES, base + (size_t)(row0 + t * TROWS) * WC, bytes, mb);
        }
    }

    // ---- distributed iface: 4 publisher blocks per batch ----
    if (bx < NPART) {
        int dbase = bx * 128;
        if (tid < 128) sx[tid] = xi[b * DIN + dbase + tid];
        __syncthreads();
        if (tid < NIF) {
            float acc = 0.f;
            #pragma unroll 16
            for (int d = 0; d < 128; d++)
                acc = fmaf(sx[d], Wm[(dbase + d) * NIF + tid], acc);
            g_part[b][bx][tid] = acc;
        }
        __threadfence();
        if (tid == 0) sflag = (atomicAdd(&g_tick_if[b], 1) == NPART - 1);
        __syncthreads();
        if (sflag) {
            // finish phase (last publisher only)
            if (tid < NIF) {
                float acc = b_lin[tid];
                #pragma unroll
                for (int p = 0; p < NPART; p++) acc += __ldcg(&g_part[b][p][tid]);
                sif[tid] = acc;
                if (tid < WC) g_q[b][tid] = acc;
                if (tid >= WC && tid < 2 * WC) swv[tid - WC] = acc;
            }
            __syncthreads();
            if (tid == 0) {
                float wg = 1.f / (1.f + expf(-sif[NIF - 1]));
                float rel[RR]; float minu = INFINITY;
                #pragma unroll
                for (int k = 0; k < RR; k++) {
                    rel[k] = usage[(size_t)b * MROWS + srp[k]];
                    minu = fminf(minu, rel[k]);
                }
                #pragma unroll
                for (int k = 0; k < RR; k++) {
                    float ig = 1.f / (1.f + expf(-sif[2 * WC + k]));
                    float I  = (rel[k] == minu) ? 1.f : 0.f;
                    sww[k] = wg * (ig * read_w[b * RR + k] + (1.f - ig) * I);
                }
            }
            __syncthreads();
            for (int t = tid; t < RR * WC; t += 256) {
                int k = t >> 6, w = t & 63;
                g_rows[b][k][w] = rvec[(b * RR + k) * WC + w] + sww[k] * swv[w];
            }
            __threadfence();
            __syncthreads();
            if (tid == 0) atomicExch(&g_qready[b], 1);
        }
    }
    // ---- everyone (publishers included) waits on the flag ----
    if (tid == 0) { while (atomicAdd(&g_qready[b], 0) == 0) __nanosleep(64); }
    __syncthreads();
    __threadfence();   // order subsequent global loads after observed flag

    // q piece: floats [(tid&15)*4, +4)
    float4 qp = __ldcg((const float4*)&g_q[b][(tid & 15) * 4]);

    float ld[8]; int lix[8];
    #pragma unroll
    for (int k = 0; k < 8; k++) { ld[k] = INFINITY; lix[k] = 0x7fffffff; }
    const bool is_prod = ((lane & 15) == 0);
    const int rbase = tid >> 4;

    for (int t = 0; t < ntiles; ++t) {
        int s = t % NSTAGE;
        uint32_t mb = smem_u32(&mbar[s]);
        mbar_wait(mb, (t / NSTAGE) & 1);

        // eager issue of tile (t-1)+NSTAGE into drained slot (t-1)%NSTAGE
        if (t > 0 && tid == 0) {
            int tn = (t - 1) + NSTAGE;
            if (tn < ntiles) {
                int s2 = (t - 1) % NSTAGE;
                int tr = min(TROWS, nrows - tn * TROWS);
                uint32_t bytes = (uint32_t)tr * WC * 4;
                uint32_t mb2 = smem_u32(&mbar[s2]);
                mbar_expect_tx(mb2, bytes);
                bulk_g2s(smem_base + s2 * TBYTES, base + (size_t)(row0 + tn * TROWS) * WC, bytes, mb2);
            }
        }

        const char* stg = dynsmem + s * TBYTES;
        float acc0, acc1, acc2, acc3;
        {
            const float4 v0 = *(const float4*)(stg + tid * 16);
            const float4 v1 = *(const float4*)(stg + tid * 16 + 4096);
            const float4 v2 = *(const float4*)(stg + tid * 16 + 8192);
            const float4 v3 = *(const float4*)(stg + tid * 16 + 12288);
            float dx;
            dx = v0.x - qp.x; acc0  = dx * dx;
            dx = v0.y - qp.y; acc0 += dx * dx;
            dx = v0.z - qp.z; acc0 += dx * dx;
            dx = v0.w - qp.w; acc0 += dx * dx;
            dx = v1.x - qp.x; acc1  = dx * dx;
            dx = v1.y - qp.y; acc1 += dx * dx;
            dx = v1.z - qp.z; acc1 += dx * dx;
            dx = v1.w - qp.w; acc1 += dx * dx;
            dx = v2.x - qp.x; acc2  = dx * dx;
            dx = v2.y - qp.y; acc2 += dx * dx;
            dx = v2.z - qp.z; acc2 += dx * dx;
            dx = v2.w - qp.w; acc2 += dx * dx;
            dx = v3.x - qp.x; acc3  = dx * dx;
            dx = v3.y - qp.y; acc3 += dx * dx;
            dx = v3.z - qp.z; acc3 += dx * dx;
            dx = v3.w - qp.w; acc3 += dx * dx;
        }
        #pragma unroll
        for (int off = 1; off <= 8; off <<= 1) {
            acc0 += __shfl_xor_sync(0xffffffffu, acc0, off);
            acc1 += __shfl_xor_sync(0xffffffffu, acc1, off);
            acc2 += __shfl_xor_sync(0xffffffffu, acc2, off);
            acc3 += __shfl_xor_sync(0xffffffffu, acc3, off);
        }
        if (is_prod) {
            int g0 = row0 + t * TROWS + rbase;
            float av[4] = {acc0, acc1, acc2, acc3};
            #pragma unroll
            for (int k = 0; k < 4; k++) {
                int gr = g0 + 16 * k;
                float cv = av[k];
                if (gr < row_end && lt_pair(cv, gr, ld[7], lix[7])) {
                    bool stale = false;
                    #pragma unroll
                    for (int j = 0; j < RR; j++) stale |= (srp[j] == gr);
                    if (!stale) {
                        int ci = gr;
                        #pragma unroll
                        for (int j = 0; j < 8; j++) {
                            bool sw = lt_pair(cv, ci, ld[j], lix[j]);
                            float td = ld[j]; int ti = lix[j];
                            if (sw) { ld[j] = cv; lix[j] = ci; cv = td; ci = ti; }
                        }
                    }
                }
            }
        }
        __syncthreads();   // stage s fully consumed
    }

    // producers dump sorted-8 to pool [0,128)
    if (is_prod) {
        #pragma unroll
        for (int k = 0; k < 8; k++) { sd[rbase * 8 + k] = ld[k]; si[rbase * 8 + k] = lix[k]; }
    }

    // warp 0: patch candidates for rp rows in range (slots [128,137))
    if (warp == 0) {
        #pragma unroll
        for (int k = 0; k < RR; k++) {
            int rr = srp[k];
            bool use = (rr >= row0 && rr < row_end);
            #pragma unroll
            for (int k2 = k + 1; k2 < RR; k2++) use &= (srp[k2] != rr);  // last write wins
            float accv = 0.f;
            if (lane < 16) {
                float4 g0 = __ldcg((const float4*)&g_rows[b][k][lane * 4]);
                float dx;
                dx = g0.x - qp.x; accv  = dx * dx;
                dx = g0.y - qp.y; accv += dx * dx;
                dx = g0.z - qp.z; accv += dx * dx;
                dx = g0.w - qp.w; accv += dx * dx;
                #pragma unroll
                for (int off = 1; off <= 8; off <<= 1)
                    accv += __shfl_xor_sync(0xFFFFu, accv, off);
            }
            if (lane == 0) {
                sd[NPROD * 8 + k] = use ? accv : INFINITY;
                si[NPROD * 8 + k] = use ? rr   : 0x7fffffff;
            }
        }
    }
    __syncthreads();

    // merge pool (137) -> block top-8 -> global candidates
    if (tid < 32) {
        int l = tid;
        for (int s = 0; s < 8; s++) {
            float bd = INFINITY; int bi = 0x7fffffff; int bs = -1;
            for (int k = l; k < NPOOL; k += 32)
                if (lt_pair(sd[k], si[k], bd, bi)) { bd = sd[k]; bi = si[k]; bs = k; }
            #pragma unroll
            for (int off = 16; off; off >>= 1) {
                float od = __shfl_xor_sync(0xffffffffu, bd, off);
                int   oi = __shfl_xor_sync(0xffffffffu, bi, off);
                int   os = __shfl_xor_sync(0xffffffffu, bs, off);
                if (lt_pair(od, oi, bd, bi)) { bd = od; bi = oi; bs = os; }
            }
            if (l == 0) {
                g_cand_d[b][bx * 8 + s] = bd;
                g_cand_i[b][bx * 8 + s] = bi;
                if (bs >= 0) sd[bs] = INFINITY;
            }
            __syncwarp();
        }
    }

    // ticket: last block of batch b does final merge + gather, resets state
    __threadfence();
    if (tid == 0) sflag = (atomicAdd(&g_tick_sc[b], 1) == NBLK - 1);
    __syncthreads();
    if (!sflag) return;
    if (tid == 0) { g_tick_sc[b] = 0; g_qready[b] = 0; g_tick_if[b] = 0; }

    if (tid < NCAND) {
        sd[tid] = __ldcg(&g_cand_d[b][tid]);
        si[tid] = __ldcg(&g_cand_i[b][tid]);
    }
    __syncthreads();

    if (tid < 32) {
        int l = tid;
        for (int s = 0; s < 8; s++) {
            float bd = INFINITY; int bi = 0x7fffffff; int bs = -1;
            for (int k = l; k < NCAND; k += 32)
                if (lt_pair(sd[k], si[k], bd, bi)) { bd = sd[k]; bi = si[k]; bs = k; }
            #pragma unroll
            for (int off = 16; off; off >>= 1) {
                float od = __shfl_xor_sync(0xffffffffu, bd, off);
                int   oi = __shfl_xor_sync(0xffffffffu, bi, off);
                int   os = __shfl_xor_sync(0xffffffffu, bs, off);
                if (lt_pair(od, oi, bd, bi)) { bd = od; bi = oi; bs = os; }
            }
            if (l == 0) { sel[s] = bi; if (bs >= 0) sd[bs] = INFINITY; }
            __syncwarp();
        }
    }
    __syncthreads();

    for (int t = tid; t < 8 * WC; t += blockDim.x) {
        int k = t >> 6, w = t & 63;
        int idx = sel[k];
        int src = -1;
        #pragma unroll
        for (int j = RR - 1; j >= 0; --j)
            if (src < 0 && srp[j] == idx) src = j;
        float v = (src >= 0) ? __ldcg(&g_rows[b][src][w])
                             : __ldcg(&mem[((size_t)b * MROWS + idx) * WC + w]);
        out[(b * 8 + k) * WC + w] = v;
    }
}

// ================= launcher =================
extern "C" void kernel_launch(void* const* d_in, const int* in_sizes, int n_in,
                              void* d_out, int out_size) {
    const float* xi     = (const float*)d_in[0];
    const float* Wm     = (const float*)d_in[1];
    const float* b_lin  = (const float*)d_in[2];
    const float* mem    = (const float*)d_in[3];
    const float* usage  = (const float*)d_in[4];
    const float* read_w = (const float*)d_in[5];
    const float* rvec   = (const float*)d_in[7];
    const int*   rpos   = (const int*)d_in[9];
    float* out = (float*)d_out;

    static int smem_set = 0;
    if (!smem_set) {
        cudaFuncSetAttribute(k_scan, cudaFuncAttributeMaxDynamicSharedMemorySize, SMEM_DYN);
        smem_set = 1;
    }

    k_scan<<<dim3(NBLK, NB), 256, SMEM_DYN>>>(mem, rpos, out, xi, Wm, b_lin,
                                              usage, read_w, rvec);
}